// round 9
// baseline (speedup 1.0000x reference)
#include <cuda_runtime.h>
#include <math.h>

#define BSZ 4096
#define HSZ 512
#define KSZ 32
#define DSZ 20
#define NPAIR 496   // 32*31/2
#define NBB 64
#define TPB 256

typedef unsigned long long u64;

// ---------------- device scratch (no allocations allowed) ----------------
__device__ float  g_pm[NBB][HSZ][KSZ];   // partial class sums  [bb][h][k]
__device__ float  g_ps[NBB][HSZ][KSZ];   // partial sum h^2c^2  [bb][h][k]
__device__ double g_pcnt[NBB][KSZ];
__device__ float  g_m[KSZ][HSZ];
__device__ float  g_w[KSZ][HSZ];
__device__ float  g_inv[4096];           // 1/j reciprocal table

__device__ unsigned long long g_acc;     // fixed-point (2^-32) accumulator
__device__ unsigned int g_done;

__device__ __forceinline__ u64 ffma2(u64 a, u64 b, u64 c) {
    u64 d;
    asm("fma.rn.f32x2 %0, %1, %2, %3;" : "=l"(d) : "l"(a), "l"(b), "l"(c));
    return d;
}
__device__ __forceinline__ float f2lo(u64 v) { return __uint_as_float((unsigned)v); }
__device__ __forceinline__ float f2hi(u64 v) { return __uint_as_float((unsigned)(v >> 32)); }

union F4U { float4 f; u64 d[2]; };

// ln B(1/2, b) without lgamma (fallback path only).
__device__ __forceinline__ double lbeta_half(double b) {
    double z = b, prod = 1.0;
#pragma unroll 1
    while (z < 32.0) { prod *= z / (z + 0.5); z += 1.0; }
    double iz = 1.0 / z;
    double ser = 1.0 + iz * (-0.125 + iz * (0.0078125 +
                 iz * (0.0048828125 + iz * (-0.000640869140625))));
    return 0.57236494292470008707 - log(prod * sqrt(z) * ser);
}

// Per-thread Lentz CF (no warp votes -> divergence-safe). Fallback only.
__device__ __forceinline__ float betacf_thread(float a, float b, float x) {
    const float FPMIN = 1e-30f;
    float qab = a + b, qap = a + 1.0f, qam = a - 1.0f;
    float c = 1.0f;
    float d = 1.0f - qab * x / qap;
    if (fabsf(d) < FPMIN) d = FPMIN;
    d = 1.0f / d;
    float hh = d;
#pragma unroll 1
    for (int m = 1; m <= 200; m++) {
        float fm = (float)m, m2 = 2.0f * fm;
        float aa = fm * (b - fm) * x / ((qam + m2) * (a + m2));
        d = 1.0f + aa * d; if (fabsf(d) < FPMIN) d = FPMIN;
        c = 1.0f + aa / c; if (fabsf(c) < FPMIN) c = FPMIN;
        d = 1.0f / d;
        hh *= d * c;
        aa = -(a + fm) * (qab + fm) * x / ((a + m2) * (qap + m2));
        d = 1.0f + aa * d; if (fabsf(d) < FPMIN) d = FPMIN;
        c = 1.0f + aa / c; if (fabsf(c) < FPMIN) c = FPMIN;
        d = 1.0f / d;
        float del = d * c;
        hh *= del;
        if (fabsf(del - 1.0f) < 2.4e-7f) break;
    }
    return hh;
}

__device__ __forceinline__ void pair_ij(int p, int& ii, int& jj) {
    int i = 0, rem = p;
    while (rem >= (KSZ - 1 - i)) { rem -= (KSZ - 1 - i); i++; }
    ii = i; jj = i + 1 + rem;
}

// ================== K1: stats (grid (NBB,4), barrier-free) =================
__global__ __launch_bounds__(TPB) void stats_kernel(const float* __restrict__ hidden,
                                                    const float* __restrict__ cluster) {
    __shared__ float sh_hidp[32][256];   // packed pairs {h, h^2}
    __shared__ float sh_cp[32][64];      // packed pairs {c, c^2}
    __shared__ double sh_cnt[TPB];

    const int tid = (int)threadIdx.x;
    const int bb = (int)blockIdx.x;      // 0..63
    const int hb = (int)blockIdx.y;      // 0..3
    const int h0 = hb * 128;
    const int b0 = bb * 64;
    const int hg = tid >> 3;             // owns 4 h
    const int kg = tid & 7;              // owns 4 k

    if (bb == 0 && hb == 0 && tid == 0) { g_acc = 0ULL; g_done = 0u; }

    u64 acc[4][4];
#pragma unroll
    for (int i = 0; i < 4; i++)
#pragma unroll
        for (int j = 0; j < 4; j++) acc[i][j] = 0ULL;

    for (int bt = 0; bt < 64; bt += 32) {
        __syncthreads();
#pragma unroll
        for (int it = 0; it < 4; it++) {
            int e = tid + it * 256;
            int r = e >> 5, c4 = e & 31;
            float4 v = *(const float4*)&hidden[(b0 + bt + r) * HSZ + h0 + c4 * 4];
            float4 w0 = make_float4(v.x, v.x * v.x, v.y, v.y * v.y);
            float4 w1 = make_float4(v.z, v.z * v.z, v.w, v.w * v.w);
            *(float4*)&sh_hidp[r][c4 * 8] = w0;
            *(float4*)&sh_hidp[r][c4 * 8 + 4] = w1;
        }
        {
            int r = tid >> 3, c4 = tid & 7;
            float4 v = *(const float4*)&cluster[(b0 + bt + r) * KSZ + c4 * 4];
            float4 w0 = make_float4(v.x, v.x * v.x, v.y, v.y * v.y);
            float4 w1 = make_float4(v.z, v.z * v.z, v.w, v.w * v.w);
            *(float4*)&sh_cp[r][c4 * 8] = w0;
            *(float4*)&sh_cp[r][c4 * 8 + 4] = w1;
        }
        __syncthreads();
#pragma unroll 4
        for (int r = 0; r < 32; r++) {
            F4U qh0, qh1, qc0, qc1;
            qh0.f = *(const float4*)&sh_hidp[r][hg * 8];
            qh1.f = *(const float4*)&sh_hidp[r][hg * 8 + 4];
            qc0.f = *(const float4*)&sh_cp[r][kg * 8];
            qc1.f = *(const float4*)&sh_cp[r][kg * 8 + 4];
            u64 hp[4] = { qh0.d[0], qh0.d[1], qh1.d[0], qh1.d[1] };
            u64 cpk[4] = { qc0.d[0], qc0.d[1], qc1.d[0], qc1.d[1] };
#pragma unroll
            for (int i = 0; i < 4; i++)
#pragma unroll
                for (int j = 0; j < 4; j++)
                    acc[i][j] = ffma2(hp[i], cpk[j], acc[i][j]);
        }
    }
#pragma unroll
    for (int i = 0; i < 4; i++) {
        int h = h0 + hg * 4 + i;
        *(float4*)&g_pm[bb][h][kg * 4] = make_float4(f2lo(acc[i][0]), f2lo(acc[i][1]), f2lo(acc[i][2]), f2lo(acc[i][3]));
        *(float4*)&g_ps[bb][h][kg * 4] = make_float4(f2hi(acc[i][0]), f2hi(acc[i][1]), f2hi(acc[i][2]), f2hi(acc[i][3]));
    }

    if (hb == 0) {
        const int k = tid & 31;
        const int seg = tid >> 5;
        double s = 0.0;
#pragma unroll
        for (int r = seg; r < 64; r += 8)
            s += (double)cluster[(b0 + r) * KSZ + k];
        __syncthreads();
        sh_cnt[tid] = s;
        __syncthreads();
        if (tid < 128) sh_cnt[tid] += sh_cnt[tid + 128];
        __syncthreads();
        if (tid < 64) sh_cnt[tid] += sh_cnt[tid + 64];
        __syncthreads();
        if (tid < 32) g_pcnt[bb][tid] = sh_cnt[tid] + sh_cnt[tid + 32];
    }
}

// ============ K2a: reduce partials -> m,w ; build 1/j table ================
// grid 144: blocks 0..127 reduce (2 threads/cell), 128..143 fill g_inv.
__global__ __launch_bounds__(TPB) void reduce_kernel() {
    int gt = (int)blockIdx.x * TPB + (int)threadIdx.x;
    if (gt < 2 * KSZ * HSZ) {
        int cell = gt >> 1;
        int half = gt & 1;
        int k = cell & 31;
        int h = cell >> 5;
        float smm = 0.f, ss = 0.f;
        int p0 = half * 32;
#pragma unroll 8
        for (int p = p0; p < p0 + 32; p++) {
            smm += g_pm[p][h][k];
            ss  += g_ps[p][h][k];
        }
        float smo = __shfl_xor_sync(0xffffffffu, smm, 1);
        float sso = __shfl_xor_sync(0xffffffffu, ss, 1);
        if (half == 0) {
            float M = smm + smo;
            float S2 = ss + sso;
            g_m[k][h] = M;
            g_w[k][h] = S2 + (float)(BSZ - 2) * M * M;
        }
    } else {
        int idx = gt - 2 * KSZ * HSZ;   // 0..4095
        g_inv[idx] = (idx > 0) ? (1.0f / (float)idx) : 0.0f;
    }
}

// ============ K2b: one pair per block (496 x 512) ===========================
__global__ __launch_bounds__(512) void pair_kernel(float* __restrict__ out) {
    __shared__ float sx[16][20];
    __shared__ float s_ci, s_cj, s_bf, s_thresh;
    __shared__ double s_bd, s_lbeta;
    __shared__ int s_nu, s_odd;
    __shared__ unsigned long long s_acc;

    const int tid = (int)threadIdx.x;
    const int lane = tid & 31, warp = tid >> 5;
    const int p = (int)blockIdx.x;
    int ii, jj; pair_ij(p, ii, jj);

    // x inputs (independent of meta; issue before the sync)
    float mi = g_m[ii][tid], mj = g_m[jj][tid];
    float wi = g_w[ii][tid], wj = g_w[jj][tid];

    // warp 0: counts via 32-lane-parallel loads + deterministic shfl tree
    if (warp == 0) {
        double si = g_pcnt[lane][ii] + g_pcnt[lane + 32][ii];
        double sj = g_pcnt[lane][jj] + g_pcnt[lane + 32][jj];
#pragma unroll
        for (int off = 16; off; off >>= 1) {
            si += __shfl_xor_sync(0xffffffffu, si, off);
            sj += __shfl_xor_sync(0xffffffffu, sj, off);
        }
        if (lane == 0) {
            float ci = (float)rint(si), cj = (float)rint(sj);
            float d2 = (ci + cj) - 2.0f;
            if (d2 == 0.0f) d2 += 1e-5f;
            double bd = 0.5 * (double)d2;
            bool isint = (d2 == rintf(d2)) && (d2 >= 1.0f) && (d2 <= 4094.0f);
            s_ci = ci; s_cj = cj;
            s_bf = (float)bd;
            s_thresh = 1.5f / ((float)bd + 2.5f);
            s_bd = bd;
            s_nu = isint ? (int)d2 : 0;
            s_odd = ((int)d2) & 1;
            s_lbeta = isint ? 0.0 : lbeta_half(bd);
            s_acc = 0ULL;
        }
    }
    __syncthreads();

    // x for h = tid, then per-warp bitonic sort (descending), top-20 to smem
    {
        float ci = s_ci, cj = s_cj;
        float gmv = 0.5f * (mi + mj);
        float di = mi - gmv, dj = mj - gmv;
        float between = di * di * ci + dj * dj * cj;
        float x = between / (between + wi + wj);
        x = fminf(fmaxf(x, 1e-37f), 1.0f - 1e-5f);
        float v = x;
#pragma unroll
        for (int kk = 2; kk <= 32; kk <<= 1)
#pragma unroll
            for (int js = kk >> 1; js > 0; js >>= 1) {
                float o = __shfl_xor_sync(0xffffffffu, v, js);
                bool up = ((lane & kk) == 0);
                bool lo = ((lane & js) == 0);
                v = (up == lo) ? fmaxf(v, o) : fminf(v, o);
            }
        if (lane < 20) sx[warp][lane] = v;
    }
    __syncthreads();

    // parallel rank-selection over 320 candidates (threads 0..319)
    if (tid < 16 * DSZ) {
        const float v = sx[tid / DSZ][tid % DSZ];
        int rank = 0;
#pragma unroll 4
        for (int c = 0; c < 16 * DSZ; c++) {
            float sv = sx[c / DSZ][c % DSZ];   // broadcast (uniform per warp step)
            rank += (sv > v) || (sv == v && c < tid);
        }
        if (rank < DSZ) {
            // ---- selected: exact I_x(1/2, nu/2) (Student-t finite series) ----
            double logI;
            float xx = v;
            float uu = 1.0f - xx;
            int nu = s_nu;
            if (nu > 0) {
                if (s_odd) {
                    int n = (nu - 1) >> 1;
                    float D = 0.0f;
                    if (n > 0) {
                        float term = 1.0f; D = 1.0f;
#pragma unroll 1
                        for (int j = 1; j < n; j++) {
                            float f = 1.0f - g_inv[2 * j + 1];
                            term *= uu * f;
                            D += term;
                        }
                    }
                    float s = sqrtf(xx), su = sqrtf(uu);
                    float A = 0.63661977236758134f * (asinf(s) + s * su * D);
                    logI = (double)logf(fminf(A, 1.0f));
                } else {
                    int n = nu >> 1;
                    float term = 1.0f, S = 1.0f;
#pragma unroll 1
                    for (int j = 1; j < n; j++) {
                        float f = fmaf(-0.5f, g_inv[j], 1.0f);
                        term *= uu * f;
                        S += term;
                    }
                    logI = (double)logf(fminf(sqrtf(xx) * S, 1.0f));
                }
            } else {
                float bf = s_bf;
                bool sel = xx < s_thresh;
                float pa = sel ? 0.5f : bf;
                float pb = sel ? bf : 0.5f;
                float px = sel ? xx : uu;
                float cf = betacf_thread(pa, pb, px);
                double lbt = 0.5 * (double)logf(xx) + s_bd * (double)log1pf(-xx) - s_lbeta;
                if (sel) {
                    logI = lbt + (double)logf(2.0f * cf);
                } else {
                    double T = exp(lbt + (double)logf(cf / bf));
                    logI = (double)log1pf(-(float)T);
                }
            }
            long long fx = __double2ll_rn(logI * 4294967296.0);
            atomicAdd(&s_acc, (unsigned long long)fx);   // integer: order-independent
        }
    }
    __syncthreads();

    if (tid == 0) {
        atomicAdd(&g_acc, s_acc);
        __threadfence();
        unsigned int t = atomicAdd(&g_done, 1u);
        if (t == NPAIR - 1) {
            long long total = (long long)atomicAdd(&g_acc, 0ULL);
            out[0] = (float)(-(double)total * (1.0 / 4294967296.0));
        }
    }
}

extern "C" void kernel_launch(void* const* d_in, const int* in_sizes, int n_in,
                              void* d_out, int out_size) {
    (void)in_sizes; (void)n_in; (void)out_size;
    const float* hidden  = (const float*)d_in[0];
    const float* cluster = (const float*)d_in[1];
    float* out = (float*)d_out;

    dim3 gA(NBB, 4);
    stats_kernel<<<gA, TPB>>>(hidden, cluster);
    reduce_kernel<<<144, TPB>>>();
    pair_kernel<<<NPAIR, 512>>>(out);
}